// round 1
// baseline (speedup 1.0000x reference)
#include <cuda_runtime.h>
#include <math.h>

#define B_  8
#define S_  2048
#define E_  512
#define H_  8
#define DH_ 64
#define W_  16
#define FF_ 2048
#define M_  (B_ * S_)   // 16384 rows

// ---------------- scratch (static device globals; no allocation) -------------
__device__ float g_xn  [(size_t)M_ * E_];        // LN output (reused for LN1/LN2)
__device__ float g_qkv [(size_t)M_ * 3 * E_];    // fused QKV
__device__ float g_attn[(size_t)M_ * E_];        // attention output (pre O-proj)
__device__ float g_x2  [(size_t)M_ * E_];        // x + attn_out (residual 1)
__device__ float g_h   [(size_t)M_ * FF_];       // MLP hidden

// ---------------- LayerNorm: one warp per row (E=512 -> 16 elems/lane) -------
__global__ void ln_kernel(const float* __restrict__ x, const float* __restrict__ w,
                          const float* __restrict__ b, float* __restrict__ out) {
    int row  = blockIdx.x * 8 + (threadIdx.x >> 5);
    int lane = threadIdx.x & 31;
    const float* xr = x + (size_t)row * E_;
    float4 v[4];
    float s = 0.f, sq = 0.f;
#pragma unroll
    for (int i = 0; i < 4; i++) {
        v[i] = *reinterpret_cast<const float4*>(xr + i * 128 + lane * 4);
        s  += v[i].x + v[i].y + v[i].z + v[i].w;
        sq += v[i].x * v[i].x + v[i].y * v[i].y + v[i].z * v[i].z + v[i].w * v[i].w;
    }
#pragma unroll
    for (int o = 16; o > 0; o >>= 1) {
        s  += __shfl_xor_sync(0xffffffffu, s,  o);
        sq += __shfl_xor_sync(0xffffffffu, sq, o);
    }
    float mean = s * (1.0f / E_);
    float var  = sq * (1.0f / E_) - mean * mean;
    float rstd = rsqrtf(var + 1e-5f);
    float* orow = out + (size_t)row * E_;
#pragma unroll
    for (int i = 0; i < 4; i++) {
        int c = i * 128 + lane * 4;
        float4 wv = *reinterpret_cast<const float4*>(w + c);
        float4 bv = *reinterpret_cast<const float4*>(b + c);
        float4 r;
        r.x = (v[i].x - mean) * rstd * wv.x + bv.x;
        r.y = (v[i].y - mean) * rstd * wv.y + bv.y;
        r.z = (v[i].z - mean) * rstd * wv.z + bv.z;
        r.w = (v[i].w - mean) * rstd * wv.w + bv.w;
        *reinterpret_cast<float4*>(orow + c) = r;
    }
}

// ---------------- GEMM: C[M,N] = A[M,K] * B[N,K]^T + bias, fused epilogue ----
// MODE 0: +bias              MODE 1: +bias +residual              MODE 2: +bias, gelu(tanh)
__device__ __forceinline__ float gelu_tanh(float x) {
    float x3 = x * x * x;
    return 0.5f * x * (1.0f + tanhf(0.7978845608028654f * (x + 0.044715f * x3)));
}

template <int MODE>
__global__ void gemm_kernel(const float* __restrict__ A, const float* __restrict__ B,
                            const float* __restrict__ bias, const float* __restrict__ R,
                            float* __restrict__ C, int M, int N, int K) {
    __shared__ float As[16][132];
    __shared__ float Bs[16][132];
    int bm = blockIdx.y, bn = blockIdx.x;
    int tid = threadIdx.x;                  // 0..255
    int tm = tid >> 4, tn = tid & 15;       // 16x16 thread grid, 8x8 each

    const float* Ab = A + (size_t)bm * 128 * K;
    const float* Bb = B + (size_t)bn * 128 * K;

    float acc[8][8];
#pragma unroll
    for (int i = 0; i < 8; i++)
#pragma unroll
        for (int j = 0; j < 8; j++) acc[i][j] = 0.f;

    for (int k0 = 0; k0 < K; k0 += 16) {
#pragma unroll
        for (int l = 0; l < 2; l++) {
            int idx = tid + l * 256;        // 0..511
            int r = idx >> 2;
            int cq = (idx & 3) * 4;
            float4 a = *reinterpret_cast<const float4*>(Ab + (size_t)r * K + k0 + cq);
            As[cq + 0][r] = a.x; As[cq + 1][r] = a.y; As[cq + 2][r] = a.z; As[cq + 3][r] = a.w;
            float4 bv = *reinterpret_cast<const float4*>(Bb + (size_t)r * K + k0 + cq);
            Bs[cq + 0][r] = bv.x; Bs[cq + 1][r] = bv.y; Bs[cq + 2][r] = bv.z; Bs[cq + 3][r] = bv.w;
        }
        __syncthreads();
#pragma unroll
        for (int kk = 0; kk < 16; kk++) {
            float ar[8], br[8];
            *reinterpret_cast<float4*>(ar)     = *reinterpret_cast<const float4*>(&As[kk][tm * 8]);
            *reinterpret_cast<float4*>(ar + 4) = *reinterpret_cast<const float4*>(&As[kk][tm * 8 + 4]);
            *reinterpret_cast<float4*>(br)     = *reinterpret_cast<const float4*>(&Bs[kk][tn * 8]);
            *reinterpret_cast<float4*>(br + 4) = *reinterpret_cast<const float4*>(&Bs[kk][tn * 8 + 4]);
#pragma unroll
            for (int i = 0; i < 8; i++)
#pragma unroll
                for (int j = 0; j < 8; j++) acc[i][j] = fmaf(ar[i], br[j], acc[i][j]);
        }
        __syncthreads();
    }

    int row0 = bm * 128 + tm * 8;
    int col0 = bn * 128 + tn * 8;
    float bz[8];
#pragma unroll
    for (int j = 0; j < 8; j++) bz[j] = bias[col0 + j];
#pragma unroll
    for (int i = 0; i < 8; i++) {
        size_t off = (size_t)(row0 + i) * N + col0;
        float o[8];
#pragma unroll
        for (int j = 0; j < 8; j++) {
            float t = acc[i][j] + bz[j];
            if (MODE == 2) t = gelu_tanh(t);
            o[j] = t;
        }
        if (MODE == 1) {
#pragma unroll
            for (int j = 0; j < 8; j++) o[j] += R[off + j];
        }
        *reinterpret_cast<float4*>(C + off)     = *reinterpret_cast<float4*>(o);
        *reinterpret_cast<float4*>(C + off + 4) = *reinterpret_cast<float4*>(o + 4);
    }
}

// ---------------- sliding-window attention: one warp per (b, h, query) -------
// allowed keys: t in [i, min(i+W, S))   (upper window)
__global__ void attn_kernel(const float* __restrict__ qkv, float* __restrict__ out) {
    int gwarp = (blockIdx.x * blockDim.x + threadIdx.x) >> 5;   // 0 .. B*H*S-1
    int lane  = threadIdx.x & 31;
    int i  = gwarp & (S_ - 1);
    int bh = gwarp / S_;
    int h  = bh & (H_ - 1);
    int b  = bh / H_;

    const float* base = qkv + (size_t)b * S_ * 3 * E_;
    const float* qp = base + (size_t)i * 3 * E_ + h * DH_;
    float q0 = qp[lane], q1 = qp[lane + 32];

    int nt = min(W_, S_ - i);
    float sc[W_];
    float mx = -1e30f;
    for (int t = 0; t < nt; t++) {
        const float* kp = base + (size_t)(i + t) * 3 * E_ + E_ + h * DH_;
        float p = q0 * kp[lane] + q1 * kp[lane + 32];
#pragma unroll
        for (int o = 16; o > 0; o >>= 1) p += __shfl_xor_sync(0xffffffffu, p, o);
        p *= 0.125f;                      // 1/sqrt(64)
        sc[t] = p;
        mx = fmaxf(mx, p);
    }
    float sum = 0.f;
    for (int t = 0; t < nt; t++) { sc[t] = __expf(sc[t] - mx); sum += sc[t]; }
    float inv = 1.0f / sum;
    float o0 = 0.f, o1 = 0.f;
    for (int t = 0; t < nt; t++) {
        const float* vp = base + (size_t)(i + t) * 3 * E_ + 2 * E_ + h * DH_;
        o0 = fmaf(sc[t], vp[lane],      o0);
        o1 = fmaf(sc[t], vp[lane + 32], o1);
    }
    float* op = out + ((size_t)(b * S_ + i)) * E_ + h * DH_;
    op[lane]      = o0 * inv;
    op[lane + 32] = o1 * inv;
}

// ---------------- launch --------------------------------------------------
extern "C" void kernel_launch(void* const* d_in, const int* in_sizes, int n_in,
                              void* d_out, int out_size) {
    const float* x     = (const float*)d_in[0];
    const float* ln1_w = (const float*)d_in[1];
    const float* ln1_b = (const float*)d_in[2];
    const float* ln2_w = (const float*)d_in[3];
    const float* ln2_b = (const float*)d_in[4];
    const float* w_qkv = (const float*)d_in[5];
    const float* b_qkv = (const float*)d_in[6];
    const float* w_o   = (const float*)d_in[7];
    const float* b_o   = (const float*)d_in[8];
    const float* w1    = (const float*)d_in[9];
    const float* b1    = (const float*)d_in[10];
    const float* w2    = (const float*)d_in[11];
    const float* b2    = (const float*)d_in[12];
    float* out = (float*)d_out;

    float *xn, *qkv, *attn, *x2, *hbuf;
    cudaGetSymbolAddress((void**)&xn,   g_xn);
    cudaGetSymbolAddress((void**)&qkv,  g_qkv);
    cudaGetSymbolAddress((void**)&attn, g_attn);
    cudaGetSymbolAddress((void**)&x2,   g_x2);
    cudaGetSymbolAddress((void**)&hbuf, g_h);

    // 1) LN1
    ln_kernel<<<M_ / 8, 256>>>(x, ln1_w, ln1_b, xn);
    // 2) QKV projection: [M, 1536] = xn[M,512] @ w_qkv[1536,512]^T
    gemm_kernel<0><<<dim3(3 * E_ / 128, M_ / 128), 256>>>(xn, w_qkv, b_qkv, nullptr, qkv,
                                                          M_, 3 * E_, E_);
    // 3) sliding-window attention
    attn_kernel<<<(B_ * H_ * S_) / 8, 256>>>(qkv, attn);
    // 4) O projection + residual: x2 = x + attn @ w_o^T + b_o
    gemm_kernel<1><<<dim3(E_ / 128, M_ / 128), 256>>>(attn, w_o, b_o, x, x2,
                                                      M_, E_, E_);
    // 5) LN2
    ln_kernel<<<M_ / 8, 256>>>(x2, ln2_w, ln2_b, xn);
    // 6) MLP up + GELU: h = gelu(xn @ w1^T + b1)
    gemm_kernel<2><<<dim3(FF_ / 128, M_ / 128), 256>>>(xn, w1, b1, nullptr, hbuf,
                                                       M_, FF_, E_);
    // 7) MLP down + residual: out = x2 + h @ w2^T + b2
    gemm_kernel<1><<<dim3(E_ / 128, M_ / 128), 256>>>(hbuf, w2, b2, x2, out,
                                                      M_, E_, FF_);
}

// round 5
// speedup vs baseline: 4.4698x; 4.4698x over previous
#include <cuda_runtime.h>
#include <cuda_bf16.h>
#include <cstdint>
#include <math.h>

#define B_  8
#define S_  2048
#define E_  512
#define H_  8
#define DH_ 64
#define W_  16
#define FF_ 2048
#define M_  (B_ * S_)   // 16384 rows

// ---------------- scratch ----------------------------------------------------
__device__ __nv_bfloat16 g_xn  [(size_t)M_ * E_];
__device__ float         g_qkv [(size_t)M_ * 3 * E_];
__device__ __nv_bfloat16 g_attn[(size_t)M_ * E_];
__device__ float         g_x2  [(size_t)M_ * E_];
__device__ __nv_bfloat16 g_h   [(size_t)M_ * FF_];
__device__ __nv_bfloat16 g_wqkv[(size_t)3 * E_ * E_];
__device__ __nv_bfloat16 g_wo  [(size_t)E_ * E_];
__device__ __nv_bfloat16 g_w1  [(size_t)FF_ * E_];
__device__ __nv_bfloat16 g_w2  [(size_t)E_ * FF_];

// ---------------- helpers ----------------------------------------------------
__device__ __forceinline__ uint32_t pack_bf16x2(float lo, float hi) {
    uint32_t r;
    asm("cvt.rn.bf16x2.f32 %0, %1, %2;" : "=r"(r) : "f"(hi), "f"(lo));
    return r;
}
__device__ __forceinline__ uint32_t smem_to_u32(const void* p) {
    uint32_t a;
    asm("{ .reg .u64 t; cvta.to.shared.u64 t, %1; cvt.u32.u64 %0, t; }" : "=r"(a) : "l"(p));
    return a;
}
#define SMEM_SWIZZLE_128B(off) ((off) ^ (((off) >> 3) & 0x70))

__device__ __forceinline__ void ldsm_x4(uint32_t& r0, uint32_t& r1, uint32_t& r2,
                                        uint32_t& r3, uint32_t addr) {
    asm volatile("ldmatrix.sync.aligned.m8n8.x4.shared.b16 {%0,%1,%2,%3}, [%4];"
                 : "=r"(r0), "=r"(r1), "=r"(r2), "=r"(r3) : "r"(addr));
}
__device__ __forceinline__ void mma16816(float* d, uint32_t a0, uint32_t a1,
                                         uint32_t a2, uint32_t a3,
                                         uint32_t b0, uint32_t b1) {
    asm volatile(
        "mma.sync.aligned.m16n8k16.row.col.f32.bf16.bf16.f32 "
        "{%0,%1,%2,%3}, {%4,%5,%6,%7}, {%8,%9}, {%0,%1,%2,%3};"
        : "+f"(d[0]), "+f"(d[1]), "+f"(d[2]), "+f"(d[3])
        : "r"(a0), "r"(a1), "r"(a2), "r"(a3), "r"(b0), "r"(b1));
}
#define CP_ASYNC16(dst, src) \
    asm volatile("cp.async.cg.shared.global [%0], [%1], 16;" :: "r"(dst), "l"(src))
#define CP_COMMIT()  asm volatile("cp.async.commit_group;" ::: "memory")
#define CP_WAIT(n)   asm volatile("cp.async.wait_group %0;" :: "n"(n) : "memory")

// ---------------- fp32 -> bf16 weight convert --------------------------------
__global__ void cvt_kernel(const float* __restrict__ in, __nv_bfloat16* __restrict__ out, int n8) {
    int i = blockIdx.x * blockDim.x + threadIdx.x;
    if (i >= n8) return;
    float4 a = *reinterpret_cast<const float4*>(in + (size_t)i * 8);
    float4 b = *reinterpret_cast<const float4*>(in + (size_t)i * 8 + 4);
    uint32_t p[4];
    p[0] = pack_bf16x2(a.x, a.y);
    p[1] = pack_bf16x2(a.z, a.w);
    p[2] = pack_bf16x2(b.x, b.y);
    p[3] = pack_bf16x2(b.z, b.w);
    *reinterpret_cast<uint4*>(out + (size_t)i * 8) = *reinterpret_cast<uint4*>(p);
}

// ---------------- LayerNorm (fp32 in, bf16 out) ------------------------------
__global__ void ln_kernel(const float* __restrict__ x, const float* __restrict__ w,
                          const float* __restrict__ b, __nv_bfloat16* __restrict__ out) {
    int row  = blockIdx.x * 8 + (threadIdx.x >> 5);
    int lane = threadIdx.x & 31;
    const float* xr = x + (size_t)row * E_;
    float4 v[4];
    float s = 0.f, sq = 0.f;
#pragma unroll
    for (int i = 0; i < 4; i++) {
        v[i] = *reinterpret_cast<const float4*>(xr + i * 128 + lane * 4);
        s  += v[i].x + v[i].y + v[i].z + v[i].w;
        sq += v[i].x * v[i].x + v[i].y * v[i].y + v[i].z * v[i].z + v[i].w * v[i].w;
    }
#pragma unroll
    for (int o = 16; o > 0; o >>= 1) {
        s  += __shfl_xor_sync(0xffffffffu, s,  o);
        sq += __shfl_xor_sync(0xffffffffu, sq, o);
    }
    float mean = s * (1.0f / E_);
    float var  = sq * (1.0f / E_) - mean * mean;
    float rstd = rsqrtf(var + 1e-5f);
    __nv_bfloat16* orow = out + (size_t)row * E_;
#pragma unroll
    for (int i = 0; i < 4; i++) {
        int c = i * 128 + lane * 4;
        float4 wv = *reinterpret_cast<const float4*>(w + c);
        float4 bv = *reinterpret_cast<const float4*>(b + c);
        uint32_t p[2];
        p[0] = pack_bf16x2((v[i].x - mean) * rstd * wv.x + bv.x,
                           (v[i].y - mean) * rstd * wv.y + bv.y);
        p[1] = pack_bf16x2((v[i].z - mean) * rstd * wv.z + bv.z,
                           (v[i].w - mean) * rstd * wv.w + bv.w);
        *reinterpret_cast<uint2*>(orow + c) = *reinterpret_cast<uint2*>(p);
    }
}

// ---------------- bf16 mma.sync GEMM -----------------------------------------
// C[M,N] = A[M,K] (bf16, K-major) * B[N,K]^T (bf16, K-major), fp32 accum.
// MODE 0: +bias -> fp32   MODE 1: +bias +R -> fp32   MODE 2: +bias, gelu -> bf16
static constexpr int TILE_BYTES = 128 * 128;          // 128 rows x 128 B (64 bf16)
static constexpr int GEMM_SMEM  = 4 * TILE_BYTES;     // 2 bufs x (A + B) = 64 KB

__device__ __forceinline__ float gelu_fast(float x) {
    float t = x + 0.044715f * x * x * x;
    float u = 1.5957691216057308f * t;
    return x * (1.0f / (1.0f + __expf(-u)));
}

template <int MODE>
__global__ void __launch_bounds__(256)
gemm_mma_kernel(const __nv_bfloat16* __restrict__ A, const __nv_bfloat16* __restrict__ B,
                const float* __restrict__ bias, const float* __restrict__ R,
                void* __restrict__ Cout, int M, int N, int K) {
    extern __shared__ __align__(1024) char smem[];
    const uint32_t smem_base = smem_to_u32(smem);
    const int tid  = threadIdx.x;
    const int lane = tid & 31;
    const int wid  = tid >> 5;
    const int wrow = wid & 1;      // 2 warp-rows of 64
    const int wcol = wid >> 1;     // 4 warp-cols of 32
    const int bm = blockIdx.y, bn = blockIdx.x;

    const __nv_bfloat16* Ab = A + (size_t)bm * 128 * K;
    const __nv_bfloat16* Bb = B + (size_t)bn * 128 * K;

    const int nchunks = K >> 6;    // K / 64

    float acc[4][4][4];
#pragma unroll
    for (int i = 0; i < 4; i++)
#pragma unroll
        for (int j = 0; j < 4; j++)
#pragma unroll
            for (int q = 0; q < 4; q++) acc[i][j][q] = 0.f;

    // ---- prefetch chunk 0 into buf 0 ----
    {
        const int k0 = 0;
#pragma unroll
        for (int l = 0; l < 4; l++) {
            int idx = tid + l * 256;
            int r = idx >> 3, ch = idx & 7;
            CP_ASYNC16(smem_base + SMEM_SWIZZLE_128B(r * 128 + ch * 16),
                       Ab + (size_t)r * K + k0 + ch * 8);
        }
#pragma unroll
        for (int l = 0; l < 4; l++) {
            int idx = tid + l * 256;
            int r = idx >> 3, ch = idx & 7;
            CP_ASYNC16(smem_base + TILE_BYTES + SMEM_SWIZZLE_128B(r * 128 + ch * 16),
                       Bb + (size_t)r * K + k0 + ch * 8);
        }
        CP_COMMIT();
    }

    for (int c = 0; c < nchunks; c++) {
        if (c + 1 < nchunks) {
            const int k0 = (c + 1) << 6;
            const uint32_t boff = ((c + 1) & 1) * 2 * TILE_BYTES;
#pragma unroll
            for (int l = 0; l < 4; l++) {
                int idx = tid + l * 256;
                int r = idx >> 3, ch = idx & 7;
                CP_ASYNC16(smem_base + boff + SMEM_SWIZZLE_128B(r * 128 + ch * 16),
                           Ab + (size_t)r * K + k0 + ch * 8);
            }
#pragma unroll
            for (int l = 0; l < 4; l++) {
                int idx = tid + l * 256;
                int r = idx >> 3, ch = idx & 7;
                CP_ASYNC16(smem_base + boff + TILE_BYTES + SMEM_SWIZZLE_128B(r * 128 + ch * 16),
                           Bb + (size_t)r * K + k0 + ch * 8);
            }
            CP_COMMIT();
            CP_WAIT(1);
        } else {
            CP_WAIT(0);
        }
        __syncthreads();

        const uint32_t bufA = smem_base + (c & 1) * 2 * TILE_BYTES;
        const uint32_t bufB = bufA + TILE_BYTES;
#pragma unroll
        for (int ks = 0; ks < 4; ks++) {          // 4 x k16 within 64-wide tile
            const int cbyte = ks * 32 + (lane >> 4) * 16;
            uint32_t afr[4][4];
#pragma unroll
            for (int mt = 0; mt < 4; mt++) {
                int r = wrow * 64 + mt * 16 + (lane & 15);
                ldsm_x4(afr[mt][0], afr[mt][1], afr[mt][2], afr[mt][3],
                        bufA + SMEM_SWIZZLE_128B(r * 128 + cbyte));
            }
            uint32_t bfr[2][4];
#pragma unroll
            for (int g = 0; g < 2; g++) {
                int r = wcol * 32 + g * 16 + (lane & 15);
                ldsm_x4(bfr[g][0], bfr[g][1], bfr[g][2], bfr[g][3],
                        bufB + SMEM_SWIZZLE_128B(r * 128 + cbyte));
            }
#pragma unroll
            for (int mt = 0; mt < 4; mt++)
#pragma unroll
                for (int nt = 0; nt < 4; nt++) {
                    uint32_t b0 = bfr[nt >> 1][nt & 1];
                    uint32_t b1 = bfr[nt >> 1][(nt & 1) + 2];
                    mma16816(acc[mt][nt], afr[mt][0], afr[mt][1], afr[mt][2],
                             afr[mt][3], b0, b1);
                }
        }
        __syncthreads();
    }

    // ---- epilogue ----
    const int col_base = bn * 128 + wcol * 32 + (lane & 3) * 2;
    const int row_base = bm * 128 + wrow * 64 + (lane >> 2);
#pragma unroll
    for (int mt = 0; mt < 4; mt++) {
#pragma unroll
        for (int nt = 0; nt < 4; nt++) {
            int col = col_base + nt * 8;
            float bz0 = bias[col], bz1 = bias[col + 1];
            int r0 = row_base + mt * 16;
            int r1 = r0 + 8;
            float v00 = acc[mt][nt][0] + bz0, v01 = acc[mt][nt][1] + bz1;
            float v10 = acc[mt][nt][2] + bz0, v11 = acc[mt][nt][3] + bz1;
            if (MODE == 2) {
                __nv_bfloat16* C = (__nv_bfloat16*)Cout;
                *reinterpret_cast<uint32_t*>(C + (size_t)r0 * N + col) =
                    pack_bf16x2(gelu_fast(v00), gelu_fast(v01));
                *reinterpret_cast<uint32_t*>(C + (size_t)r1 * N + col) =
                    pack_bf16x2(gelu_fast(v10), gelu_fast(v11));
            } else {
                float* C = (float*)Cout;
                size_t o0 = (size_t)r0 * N + col;
                size_t o1 = (size_t)r1 * N + col;
                if (MODE == 1) {
                    float2 ra = *reinterpret_cast<const float2*>(R + o0);
                    float2 rb = *reinterpret_cast<const float2*>(R + o1);
                    v00 += ra.x; v01 += ra.y; v10 += rb.x; v11 += rb.y;
                }
                *reinterpret_cast<float2*>(C + o0) = make_float2(v00, v01);
                *reinterpret_cast<float2*>(C + o1) = make_float2(v10, v11);
            }
        }
    }
}

// ---------------- sliding-window attention (fp32 in, bf16 out) ---------------
__global__ void attn_kernel(const float* __restrict__ qkv, __nv_bfloat16* __restrict__ out) {
    int gwarp = (blockIdx.x * blockDim.x + threadIdx.x) >> 5;
    int lane  = threadIdx.x & 31;
    int i  = gwarp & (S_ - 1);
    int bh = gwarp / S_;
    int h  = bh & (H_ - 1);
    int b  = bh / H_;

    const float* base = qkv + (size_t)b * S_ * 3 * E_;
    const float* qp = base + (size_t)i * 3 * E_ + h * DH_;
    float q0 = qp[lane], q1 = qp[lane + 32];

    int nt = min(W_, S_ - i);
    float sc[W_];
    float mx = -1e30f;
    for (int t = 0; t < nt; t++) {
        const float* kp = base + (size_t)(i + t) * 3 * E_ + E_ + h * DH_;
        float p = q0 * kp[lane] + q1 * kp[lane + 32];
#pragma unroll
        for (int o = 16; o > 0; o >>= 1) p += __shfl_xor_sync(0xffffffffu, p, o);
        p *= 0.125f;
        sc[t] = p;
        mx = fmaxf(mx, p);
    }
    float sum = 0.f;
    for (int t = 0; t < nt; t++) { sc[t] = __expf(sc[t] - mx); sum += sc[t]; }
    float inv = 1.0f / sum;
    float o0 = 0.f, o1 = 0.f;
    for (int t = 0; t < nt; t++) {
        const float* vp = base + (size_t)(i + t) * 3 * E_ + 2 * E_ + h * DH_;
        o0 = fmaf(sc[t], vp[lane],      o0);
        o1 = fmaf(sc[t], vp[lane + 32], o1);
    }
    __nv_bfloat16* op = out + ((size_t)(b * S_ + i)) * E_ + h * DH_;
    op[lane]      = __float2bfloat16(o0 * inv);
    op[lane + 32] = __float2bfloat16(o1 * inv);
}

// ---------------- launch -----------------------------------------------------
extern "C" void kernel_launch(void* const* d_in, const int* in_sizes, int n_in,
                              void* d_out, int out_size) {
    const float* x     = (const float*)d_in[0];
    const float* ln1_w = (const float*)d_in[1];
    const float* ln1_b = (const float*)d_in[2];
    const float* ln2_w = (const float*)d_in[3];
    const float* ln2_b = (const float*)d_in[4];
    const float* w_qkv = (const float*)d_in[5];
    const float* b_qkv = (const float*)d_in[6];
    const float* w_o   = (const float*)d_in[7];
    const float* b_o   = (const float*)d_in[8];
    const float* w1    = (const float*)d_in[9];
    const float* b1    = (const float*)d_in[10];
    const float* w2    = (const float*)d_in[11];
    const float* b2    = (const float*)d_in[12];
    float* out = (float*)d_out;

    __nv_bfloat16 *xn, *attnb, *hbuf, *wqkv, *wo, *w1b, *w2b;
    float *qkv, *x2;
    cudaGetSymbolAddress((void**)&xn,    g_xn);
    cudaGetSymbolAddress((void**)&qkv,   g_qkv);
    cudaGetSymbolAddress((void**)&attnb, g_attn);
    cudaGetSymbolAddress((void**)&x2,    g_x2);
    cudaGetSymbolAddress((void**)&hbuf,  g_h);
    cudaGetSymbolAddress((void**)&wqkv,  g_wqkv);
    cudaGetSymbolAddress((void**)&wo,    g_wo);
    cudaGetSymbolAddress((void**)&w1b,   g_w1);
    cudaGetSymbolAddress((void**)&w2b,   g_w2);

    cudaFuncSetAttribute(gemm_mma_kernel<0>, cudaFuncAttributeMaxDynamicSharedMemorySize, GEMM_SMEM);
    cudaFuncSetAttribute(gemm_mma_kernel<1>, cudaFuncAttributeMaxDynamicSharedMemorySize, GEMM_SMEM);
    cudaFuncSetAttribute(gemm_mma_kernel<2>, cudaFuncAttributeMaxDynamicSharedMemorySize, GEMM_SMEM);

    cvt_kernel<<<(3 * E_ * E_ / 8 + 255) / 256, 256>>>(w_qkv, wqkv, 3 * E_ * E_ / 8);
    cvt_kernel<<<(E_ * E_ / 8 + 255) / 256, 256>>>(w_o, wo, E_ * E_ / 8);
    cvt_kernel<<<(FF_ * E_ / 8 + 255) / 256, 256>>>(w1, w1b, FF_ * E_ / 8);
    cvt_kernel<<<(E_ * FF_ / 8 + 255) / 256, 256>>>(w2, w2b, E_ * FF_ / 8);

    // 1) LN1 -> bf16
    ln_kernel<<<M_ / 8, 256>>>(x, ln1_w, ln1_b, xn);
    // 2) QKV: [M,1536] fp32
    gemm_mma_kernel<0><<<dim3(3 * E_ / 128, M_ / 128), 256, GEMM_SMEM>>>(
        xn, wqkv, b_qkv, nullptr, qkv, M_, 3 * E_, E_);
    // 3) attention -> bf16
    attn_kernel<<<(B_ * H_ * S_) / 8, 256>>>(qkv, attnb);
    // 4) O-proj + residual: x2 = x + attn @ w_o^T + b_o
    gemm_mma_kernel<1><<<dim3(E_ / 128, M_ / 128), 256, GEMM_SMEM>>>(
        attnb, wo, b_o, x, x2, M_, E_, E_);
    // 5) LN2 -> bf16
    ln_kernel<<<M_ / 8, 256>>>(x2, ln2_w, ln2_b, xn);
    // 6) MLP up + GELU -> bf16
    gemm_mma_kernel<2><<<dim3(FF_ / 128, M_ / 128), 256, GEMM_SMEM>>>(
        xn, w1b, b1, nullptr, hbuf, M_, FF_, E_);
    // 7) MLP down + residual
    gemm_mma_kernel<1><<<dim3(E_ / 128, M_ / 128), 256, GEMM_SMEM>>>(
        hbuf, w2b, b2, x2, out, M_, E_, FF_);
}